// round 13
// baseline (speedup 1.0000x reference)
#include <cuda_runtime.h>
#include <cstdint>

#define N_PULSES 64
#define N_STATES 21
#define THREADS  256
#define WPB      (THREADS / 32)

typedef unsigned long long u64;

__device__ __forceinline__ u64 pk(float lo, float hi) {
    u64 r; asm("mov.b64 %0,{%1,%2};" : "=l"(r) : "f"(lo), "f"(hi)); return r;
}
__device__ __forceinline__ void upk(u64 v, float& lo, float& hi) {
    asm("mov.b64 {%0,%1},%2;" : "=f"(lo), "=f"(hi) : "l"(v));
}
__device__ __forceinline__ u64 fma2(u64 a, u64 b, u64 c) {
    u64 d; asm("fma.rn.f32x2 %0,%1,%2,%3;" : "=l"(d) : "l"(a), "l"(b), "l"(c)); return d;
}
__device__ __forceinline__ u64 mul2(u64 a, u64 b) {
    u64 d; asm("mul.rn.f32x2 %0,%1,%2;" : "=l"(d) : "l"(a), "l"(b)); return d;
}
__device__ __forceinline__ float read_scalar(const void* p)
{
    int iv = *(const int*)p;
    if (iv > 0 && iv < 1000000) return (float)iv;
    return *(const float*)p;
}

__global__ __launch_bounds__(THREADS, 2)
void epg_kernel(const float* __restrict__ flip,
                const float* __restrict__ phases,
                const float* __restrict__ T1,
                const float* __restrict__ T2,
                const float* __restrict__ B0,
                const float* __restrict__ B1,
                const void*  __restrict__ TRp,
                float* __restrict__ out,
                int nbatch)
{
    __shared__ u64 s_tp[N_PULSES][8];
    // Double-buffered per-warp stage; 420 live floats, padded to 512 (4th
    // float4 flush set reads in-bounds). 2*8*512*4B = 32 KB.
    __shared__ __align__(16) float s_stage[2][WPB][512];
    // Sink for producer lanes 21..31: base index up to 10, stage offsets up
    // to +399 -> needs >= 410 floats. (R12 crash: this was sized 64.)
    __shared__ float s_dump[412];

    const int tid = threadIdx.x;
    if (tid < N_PULSES) {
        float b = phases[tid];
        float sb, cb;
        sincosf(b, &sb, &cb);
        float c2b = cb * cb - sb * sb;
        float s2b = 2.0f * cb * sb;
        s_tp[tid][0] = pk(cb, cb);
        s_tp[tid][1] = pk(c2b, c2b);
        s_tp[tid][2] = pk(s2b, s2b);
        s_tp[tid][3] = pk(-sb, -sb);
        s_tp[tid][4] = pk(-cb, -cb);
        s_tp[tid][5] = pk(-c2b, -c2b);
        s_tp[tid][6] = pk(-s2b, -s2b);
        float a = flip[tid];
        s_tp[tid][7] = pk(a, a);
    }
    __syncthreads();

    const int lane = tid & 31;
    const int warp = tid >> 5;
    const int base = (blockIdx.x * WPB + warp) * 4;
    if (base >= nbatch) return;

    const int  iA0 = base;
    const int  iA1 = (base + 1 < nbatch) ? base + 1 : base;
    const bool hiA = (base + 1 < nbatch);
    const bool okB = (base + 2 < nbatch);
    const int  iB0 = okB ? base + 2 : base;
    const int  iB1 = (base + 3 < nbatch) ? base + 3 : iB0;
    const bool hiB = (base + 3 < nbatch);
    const bool fullwarp = (base + 3 < nbatch) && ((nbatch & 3) == 0);

    const float TR = read_scalar(TRp);
    const float TWO_PI_ML = 2.0f * 3.14159265358979f * 0.001f;

#define MK_CONST(S, i0, i1)                                                    \
    const float E1a##S = expf(-TR / T1[i0]), E1b##S = expf(-TR / T1[i1]);      \
    const float E2a##S = expf(-TR / T2[i0]), E2b##S = expf(-TR / T2[i1]);      \
    float spa##S, cpa##S, spb##S, cpb##S;                                      \
    sincosf(TWO_PI_ML * B0[i0] * TR, &spa##S, &cpa##S);                        \
    sincosf(TWO_PI_ML * B0[i1] * TR, &spb##S, &cpb##S);                        \
    const u64 E1p##S  = pk(E1a##S, E1b##S);                                    \
    const u64 cpr##S  = pk(E2a##S * cpa##S,  E2b##S * cpb##S);                 \
    const u64 cpi##S  = pk(E2a##S * spa##S,  E2b##S * spb##S);                 \
    const u64 cpin##S = pk(-E2a##S * spa##S, -E2b##S * spb##S);                \
    const u64 zadd##S = (lane == 0) ? pk(1.0f - E1a##S, 1.0f - E1b##S) : 0ull; \
    const float b1h0##S = 0.5f * B1[i0], b1h1##S = 0.5f * B1[i1];

    MK_CONST(A, iA0, iA1)
    MK_CONST(B, iB0, iB1)
#undef MK_CONST

    const u64 m2p  = pk(-2.0f, -2.0f);
    const u64 onep = pk(1.0f, 1.0f);

    u64 FprA = 0ull, FpiA = 0ull, FmrA = 0ull, FmiA = 0ull;
    u64 FprB = 0ull, FpiB = 0ull, FmrB = 0ull, FmiB = 0ull;
    u64 ZA = (lane == 0) ? pk(1.0f, 1.0f) : 0ull;
    u64 ZB = ZA;

    const size_t cs = (size_t)nbatch * N_STATES;
    float* oA = out + (size_t)iA0 * N_STATES + lane;        // scalar fallback
    const bool active = (lane < N_STATES);
    const bool edgeFp = (lane == 0 || lane >= N_STATES);
    const bool edgeFm = (lane >= N_STATES - 1);

    // Flush precompute: stage is gmem-linear f = c*84 + b*21 + s.
    // float4 j -> c = 4j/84, w = 4j - 84c. All offsets multiples of 4 -> aligned.
    const bool p3 = (lane < 9);
    float *gf0, *gf1, *gf2, *gf3;
    {
        float* gb = out + (size_t)base * N_STATES;
        int f0 = 4 * lane,        c0 = f0 / 84, w0 = f0 - 84 * c0;
        int f1 = 4 * (lane + 32), c1 = f1 / 84, w1 = f1 - 84 * c1;
        int f2 = 4 * (lane + 64), c2 = f2 / 84, w2 = f2 - 84 * c2;
        int f3 = p3 ? 4 * (lane + 96) : 416;
        int c3 = f3 / 84,         w3 = f3 - 84 * c3;
        gf0 = gb + (size_t)c0 * cs + w0;
        gf1 = gb + (size_t)c1 * cs + w1;
        gf2 = gb + (size_t)c2 * cs + w2;
        gf3 = gb + (size_t)c3 * cs + w3;
    }
    float* const st0 = (lane < N_STATES) ? &s_stage[0][warp][lane] : &s_dump[lane - N_STATES];
    float* const st1 = (lane < N_STATES) ? &s_stage[1][warp][lane] : &s_dump[lane - N_STATES];

#define ADVANCE(S, Fpn, Fpi_n, Fmn, Fmi_n, Zn)                                 \
    u64 Fpn, Fpi_n, Fmn, Fmi_n, Zn;                                            \
    {                                                                          \
        const u64 zr  = fma2(E1p##S, Z##S, zadd##S);                           \
        const u64 npr = fma2(cpr##S, Fpr##S, mul2(cpin##S, Fpi##S));           \
        const u64 npi = fma2(cpr##S, Fpi##S, mul2(cpi##S,  Fpr##S));           \
        const u64 nmr = fma2(cpr##S, Fmr##S, mul2(cpi##S,  Fmi##S));           \
        const u64 nmi = fma2(cpr##S, Fmi##S, mul2(cpin##S, Fmr##S));           \
        float sa0, ca0, sa1, ca1;                                              \
        __sincosf(aflip * b1h0##S, &sa0, &ca0);                                \
        __sincosf(aflip * b1h1##S, &sa1, &ca1);                                \
        const u64 sap   = pk(sa0, sa1);                                        \
        const u64 cap   = pk(ca0, ca1);                                        \
        const u64 ca2p  = mul2(cap, cap);                                      \
        const u64 sa2p  = mul2(sap, sap);                                      \
        const u64 casap = mul2(cap, sap);                                      \
        const u64 k1  = mul2(sa2p, tp1);                                       \
        const u64 k2  = mul2(sa2p, tp2);                                       \
        const u64 k1n = mul2(sa2p, tp5);                                       \
        const u64 k2n = mul2(sa2p, tp6);                                       \
        const u64 k3n = mul2(casap, tp3);                                      \
        const u64 k4  = mul2(casap, tp0);                                      \
        const u64 k4n = mul2(casap, tp4);                                      \
        const u64 k7  = fma2(sa2p, m2p, onep);                                 \
        Fpn   = fma2(k3n, zr, fma2(k2,  nmi, fma2(k1,  nmr, mul2(ca2p, npr))));\
        Fpi_n = fma2(k4,  zr, fma2(k1n, nmi, fma2(k2,  nmr, mul2(ca2p, npi))));\
        Fmn   = fma2(k3n, zr, fma2(ca2p, nmr, fma2(k2n, npi, mul2(k1, npr)))); \
        Fmi_n = fma2(k4n, zr, fma2(ca2p, nmi, fma2(k1n, npi, mul2(k2n, npr))));\
        Zn    = fma2(k7,  zr, fma2(k3n, nmr, fma2(k3n, npr,                    \
                                  fma2(k4n, nmi, mul2(k4, npi)))));            \
    }

    // Stage one step's 20 values (gmem-linear layout), branch-free via st0/st1.
#define STAGE(P)                                                               \
    {                                                                          \
        float l, h;                                                            \
        upk(FprA, l, h); P[0]   = l; P[21]  = h;                               \
        upk(FprB, l, h); P[42]  = l; P[63]  = h;                               \
        upk(FpiA, l, h); P[84]  = l; P[105] = h;                               \
        upk(FpiB, l, h); P[126] = l; P[147] = h;                               \
        upk(FmrA, l, h); P[168] = l; P[189] = h;                               \
        upk(FmrB, l, h); P[210] = l; P[231] = h;                               \
        upk(FmiA, l, h); P[252] = l; P[273] = h;                               \
        upk(FmiB, l, h); P[294] = l; P[315] = h;                               \
        upk(ZA,   l, h); P[336] = l; P[357] = h;                               \
        upk(ZB,   l, h); P[378] = l; P[399] = h;                               \
    }

    // Coalesced deferred flush of a completed buffer; advances gmem cursors.
#define FLUSH(BUF)                                                             \
    {                                                                          \
        const float4* sb = (const float4*)&s_stage[(BUF)][warp][0];            \
        float4 v0 = sb[lane];                                                  \
        float4 v1 = sb[lane + 32];                                             \
        float4 v2 = sb[lane + 64];                                             \
        float4 v3 = sb[lane + 96];                                             \
        __stcs((float4*)gf0, v0);                                              \
        __stcs((float4*)gf1, v1);                                              \
        __stcs((float4*)gf2, v2);                                              \
        if (p3) __stcs((float4*)gf3, v3);                                      \
        gf0 += 5 * cs; gf1 += 5 * cs; gf2 += 5 * cs; gf3 += 5 * cs;            \
    }

#pragma unroll 1
    for (int t = 0; t < N_PULSES; ++t) {
        if (fullwarp && t > 0)
            FLUSH((t - 1) & 1)          // data one full step old: LDS lat hidden

        const u64* tp = s_tp[t];
        const u64 tp0 = tp[0], tp1 = tp[1], tp2 = tp[2], tp3 = tp[3];
        const u64 tp4 = tp[4], tp5 = tp[5], tp6 = tp[6];
        float aflip, dummy;
        upk(tp[7], aflip, dummy);

        ADVANCE(A, FpnA, FpinA, FmnA, FminA, ZnA)
        u64 sFprA = __shfl_up_sync(0xffffffffu, FpnA, 1);
        u64 sFpiA = __shfl_up_sync(0xffffffffu, FpinA, 1);
        u64 sFmrA = __shfl_down_sync(0xffffffffu, FmnA, 1);
        u64 sFmiA = __shfl_down_sync(0xffffffffu, FminA, 1);

        ADVANCE(B, FpnB, FpinB, FmnB, FminB, ZnB)
        u64 sFprB = __shfl_up_sync(0xffffffffu, FpnB, 1);
        u64 sFpiB = __shfl_up_sync(0xffffffffu, FpinB, 1);
        u64 sFmrB = __shfl_down_sync(0xffffffffu, FmnB, 1);
        u64 sFmiB = __shfl_down_sync(0xffffffffu, FminB, 1);

        if (edgeFp) { sFprA = 0ull; sFpiA = 0ull; sFprB = 0ull; sFpiB = 0ull; }
        if (edgeFm) { sFmrA = 0ull; sFmiA = 0ull; sFmrB = 0ull; sFmiB = 0ull; }
        FprA = sFprA; FpiA = sFpiA; FmrA = sFmrA; FmiA = sFmiA; ZA = ZnA;
        FprB = sFprB; FpiB = sFpiB; FmrB = sFmrB; FmiB = sFmiB; ZB = ZnB;

        if (fullwarp) {
            if (t & 1) STAGE(st1) else STAGE(st0)
            __syncwarp();
        } else if (active) {
            float l0,h0,l1,h1,l2,h2,l3,h3,l4,h4;
            float* ot = oA + (size_t)t * 5u * cs;
            upk(FprA,l0,h0); upk(FpiA,l1,h1); upk(FmrA,l2,h2);
            upk(FmiA,l3,h3); upk(ZA, l4,h4);
            ot[0] = l0; ot[cs] = l1; ot[2*cs] = l2; ot[3*cs] = l3; ot[4*cs] = l4;
            if (hiA) {
                ot[N_STATES] = h0; ot[N_STATES+cs] = h1; ot[N_STATES+2*cs] = h2;
                ot[N_STATES+3*cs] = h3; ot[N_STATES+4*cs] = h4;
            }
            if (okB) {
                upk(FprB,l0,h0); upk(FpiB,l1,h1); upk(FmrB,l2,h2);
                upk(FmiB,l3,h3); upk(ZB, l4,h4);
                ot[2*N_STATES] = l0; ot[2*N_STATES+cs] = l1;
                ot[2*N_STATES+2*cs] = l2; ot[2*N_STATES+3*cs] = l3;
                ot[2*N_STATES+4*cs] = l4;
                if (hiB) {
                    ot[3*N_STATES] = h0; ot[3*N_STATES+cs] = h1;
                    ot[3*N_STATES+2*cs] = h2; ot[3*N_STATES+3*cs] = h3;
                    ot[3*N_STATES+4*cs] = h4;
                }
            }
        }
    }
    if (fullwarp)
        FLUSH((N_PULSES - 1) & 1)       // final buffer
#undef ADVANCE
#undef STAGE
#undef FLUSH
}

extern "C" void kernel_launch(void* const* d_in, const int* in_sizes, int n_in,
                              void* d_out, int out_size)
{
    const float* flip   = (const float*)d_in[0];
    const float* phases = (const float*)d_in[1];
    const float* T1     = (const float*)d_in[2];
    const float* T2     = (const float*)d_in[3];
    const float* B0     = (const float*)d_in[4];
    const float* B1     = (const float*)d_in[5];
    const void*  TRp    = d_in[6];

    const int nbatch = in_sizes[2];
    float* out = (float*)d_out;
    const int nwarps = (nbatch + 3) / 4;
    const int blocks = (nwarps + WPB - 1) / WPB;
    epg_kernel<<<blocks, THREADS>>>(flip, phases, T1, T2, B0, B1, TRp, out, nbatch);
}

// round 14
// speedup vs baseline: 1.0006x; 1.0006x over previous
#include <cuda_runtime.h>
#include <cstdint>

#define N_PULSES 64
#define N_STATES 21
#define THREADS  256
#define WPB      (THREADS / 32)

typedef unsigned long long u64;

__device__ __forceinline__ u64 pk(float lo, float hi) {
    u64 r; asm("mov.b64 %0,{%1,%2};" : "=l"(r) : "f"(lo), "f"(hi)); return r;
}
__device__ __forceinline__ void upk(u64 v, float& lo, float& hi) {
    asm("mov.b64 {%0,%1},%2;" : "=f"(lo), "=f"(hi) : "l"(v));
}
__device__ __forceinline__ u64 fma2(u64 a, u64 b, u64 c) {
    u64 d; asm("fma.rn.f32x2 %0,%1,%2,%3;" : "=l"(d) : "l"(a), "l"(b), "l"(c)); return d;
}
__device__ __forceinline__ u64 mul2(u64 a, u64 b) {
    u64 d; asm("mul.rn.f32x2 %0,%1,%2;" : "=l"(d) : "l"(a), "l"(b)); return d;
}
__device__ __forceinline__ float read_scalar(const void* p)
{
    int iv = *(const int*)p;
    if (iv > 0 && iv < 1000000) return (float)iv;
    return *(const float*)p;
}

__global__ __launch_bounds__(THREADS, 2)
void epg_kernel(const float* __restrict__ flip,
                const float* __restrict__ phases,
                const float* __restrict__ T1,
                const float* __restrict__ T2,
                const float* __restrict__ B0,
                const float* __restrict__ B1,
                const void*  __restrict__ TRp,
                float* __restrict__ out,
                int nbatch)
{
    __shared__ u64 s_tp[N_PULSES][8];
    // Double-buffered per-warp stage; 420 live floats, padded to 512 (4th
    // float4 flush set reads in-bounds). 2*8*512*4B = 32 KB.
    __shared__ __align__(16) float s_stage[2][WPB][512];
    // Sink for producer lanes 21..31: base index up to 10, stage offsets up
    // to +399 -> needs >= 410 floats. (R12 crash: this was sized 64.)
    __shared__ float s_dump[412];

    const int tid = threadIdx.x;
    if (tid < N_PULSES) {
        float b = phases[tid];
        float sb, cb;
        sincosf(b, &sb, &cb);
        float c2b = cb * cb - sb * sb;
        float s2b = 2.0f * cb * sb;
        s_tp[tid][0] = pk(cb, cb);
        s_tp[tid][1] = pk(c2b, c2b);
        s_tp[tid][2] = pk(s2b, s2b);
        s_tp[tid][3] = pk(-sb, -sb);
        s_tp[tid][4] = pk(-cb, -cb);
        s_tp[tid][5] = pk(-c2b, -c2b);
        s_tp[tid][6] = pk(-s2b, -s2b);
        float a = flip[tid];
        s_tp[tid][7] = pk(a, a);
    }
    __syncthreads();

    const int lane = tid & 31;
    const int warp = tid >> 5;
    const int base = (blockIdx.x * WPB + warp) * 4;
    if (base >= nbatch) return;

    const int  iA0 = base;
    const int  iA1 = (base + 1 < nbatch) ? base + 1 : base;
    const bool hiA = (base + 1 < nbatch);
    const bool okB = (base + 2 < nbatch);
    const int  iB0 = okB ? base + 2 : base;
    const int  iB1 = (base + 3 < nbatch) ? base + 3 : iB0;
    const bool hiB = (base + 3 < nbatch);
    const bool fullwarp = (base + 3 < nbatch) && ((nbatch & 3) == 0);

    const float TR = read_scalar(TRp);
    const float TWO_PI_ML = 2.0f * 3.14159265358979f * 0.001f;

#define MK_CONST(S, i0, i1)                                                    \
    const float E1a##S = expf(-TR / T1[i0]), E1b##S = expf(-TR / T1[i1]);      \
    const float E2a##S = expf(-TR / T2[i0]), E2b##S = expf(-TR / T2[i1]);      \
    float spa##S, cpa##S, spb##S, cpb##S;                                      \
    sincosf(TWO_PI_ML * B0[i0] * TR, &spa##S, &cpa##S);                        \
    sincosf(TWO_PI_ML * B0[i1] * TR, &spb##S, &cpb##S);                        \
    const u64 E1p##S  = pk(E1a##S, E1b##S);                                    \
    const u64 cpr##S  = pk(E2a##S * cpa##S,  E2b##S * cpb##S);                 \
    const u64 cpi##S  = pk(E2a##S * spa##S,  E2b##S * spb##S);                 \
    const u64 cpin##S = pk(-E2a##S * spa##S, -E2b##S * spb##S);                \
    const u64 zadd##S = (lane == 0) ? pk(1.0f - E1a##S, 1.0f - E1b##S) : 0ull; \
    const float b1h0##S = 0.5f * B1[i0], b1h1##S = 0.5f * B1[i1];

    MK_CONST(A, iA0, iA1)
    MK_CONST(B, iB0, iB1)
#undef MK_CONST

    const u64 m2p  = pk(-2.0f, -2.0f);
    const u64 onep = pk(1.0f, 1.0f);

    u64 FprA = 0ull, FpiA = 0ull, FmrA = 0ull, FmiA = 0ull;
    u64 FprB = 0ull, FpiB = 0ull, FmrB = 0ull, FmiB = 0ull;
    u64 ZA = (lane == 0) ? pk(1.0f, 1.0f) : 0ull;
    u64 ZB = ZA;

    const size_t cs = (size_t)nbatch * N_STATES;
    float* oA = out + (size_t)iA0 * N_STATES + lane;        // scalar fallback
    const bool active = (lane < N_STATES);
    const bool edgeFp = (lane == 0 || lane >= N_STATES);
    const bool edgeFm = (lane >= N_STATES - 1);

    // Flush precompute: stage is gmem-linear f = c*84 + b*21 + s.
    // float4 j -> c = 4j/84, w = 4j - 84c. All offsets multiples of 4 -> aligned.
    const bool p3 = (lane < 9);
    float *gf0, *gf1, *gf2, *gf3;
    {
        float* gb = out + (size_t)base * N_STATES;
        int f0 = 4 * lane,        c0 = f0 / 84, w0 = f0 - 84 * c0;
        int f1 = 4 * (lane + 32), c1 = f1 / 84, w1 = f1 - 84 * c1;
        int f2 = 4 * (lane + 64), c2 = f2 / 84, w2 = f2 - 84 * c2;
        int f3 = p3 ? 4 * (lane + 96) : 416;
        int c3 = f3 / 84,         w3 = f3 - 84 * c3;
        gf0 = gb + (size_t)c0 * cs + w0;
        gf1 = gb + (size_t)c1 * cs + w1;
        gf2 = gb + (size_t)c2 * cs + w2;
        gf3 = gb + (size_t)c3 * cs + w3;
    }
    float* const st0 = (lane < N_STATES) ? &s_stage[0][warp][lane] : &s_dump[lane - N_STATES];
    float* const st1 = (lane < N_STATES) ? &s_stage[1][warp][lane] : &s_dump[lane - N_STATES];

#define ADVANCE(S, Fpn, Fpi_n, Fmn, Fmi_n, Zn)                                 \
    u64 Fpn, Fpi_n, Fmn, Fmi_n, Zn;                                            \
    {                                                                          \
        const u64 zr  = fma2(E1p##S, Z##S, zadd##S);                           \
        const u64 npr = fma2(cpr##S, Fpr##S, mul2(cpin##S, Fpi##S));           \
        const u64 npi = fma2(cpr##S, Fpi##S, mul2(cpi##S,  Fpr##S));           \
        const u64 nmr = fma2(cpr##S, Fmr##S, mul2(cpi##S,  Fmi##S));           \
        const u64 nmi = fma2(cpr##S, Fmi##S, mul2(cpin##S, Fmr##S));           \
        float sa0, ca0, sa1, ca1;                                              \
        __sincosf(aflip * b1h0##S, &sa0, &ca0);                                \
        __sincosf(aflip * b1h1##S, &sa1, &ca1);                                \
        const u64 sap   = pk(sa0, sa1);                                        \
        const u64 cap   = pk(ca0, ca1);                                        \
        const u64 ca2p  = mul2(cap, cap);                                      \
        const u64 sa2p  = mul2(sap, sap);                                      \
        const u64 casap = mul2(cap, sap);                                      \
        const u64 k1  = mul2(sa2p, tp1);                                       \
        const u64 k2  = mul2(sa2p, tp2);                                       \
        const u64 k1n = mul2(sa2p, tp5);                                       \
        const u64 k2n = mul2(sa2p, tp6);                                       \
        const u64 k3n = mul2(casap, tp3);                                      \
        const u64 k4  = mul2(casap, tp0);                                      \
        const u64 k4n = mul2(casap, tp4);                                      \
        const u64 k7  = fma2(sa2p, m2p, onep);                                 \
        Fpn   = fma2(k3n, zr, fma2(k2,  nmi, fma2(k1,  nmr, mul2(ca2p, npr))));\
        Fpi_n = fma2(k4,  zr, fma2(k1n, nmi, fma2(k2,  nmr, mul2(ca2p, npi))));\
        Fmn   = fma2(k3n, zr, fma2(ca2p, nmr, fma2(k2n, npi, mul2(k1, npr)))); \
        Fmi_n = fma2(k4n, zr, fma2(ca2p, nmi, fma2(k1n, npi, mul2(k2n, npr))));\
        Zn    = fma2(k7,  zr, fma2(k3n, nmr, fma2(k3n, npr,                    \
                                  fma2(k4n, nmi, mul2(k4, npi)))));            \
    }

    // Stage one step's 20 values (gmem-linear layout), branch-free via st0/st1.
#define STAGE(P)                                                               \
    {                                                                          \
        float l, h;                                                            \
        upk(FprA, l, h); P[0]   = l; P[21]  = h;                               \
        upk(FprB, l, h); P[42]  = l; P[63]  = h;                               \
        upk(FpiA, l, h); P[84]  = l; P[105] = h;                               \
        upk(FpiB, l, h); P[126] = l; P[147] = h;                               \
        upk(FmrA, l, h); P[168] = l; P[189] = h;                               \
        upk(FmrB, l, h); P[210] = l; P[231] = h;                               \
        upk(FmiA, l, h); P[252] = l; P[273] = h;                               \
        upk(FmiB, l, h); P[294] = l; P[315] = h;                               \
        upk(ZA,   l, h); P[336] = l; P[357] = h;                               \
        upk(ZB,   l, h); P[378] = l; P[399] = h;                               \
    }

    // Coalesced deferred flush of a completed buffer; advances gmem cursors.
#define FLUSH(BUF)                                                             \
    {                                                                          \
        const float4* sb = (const float4*)&s_stage[(BUF)][warp][0];            \
        float4 v0 = sb[lane];                                                  \
        float4 v1 = sb[lane + 32];                                             \
        float4 v2 = sb[lane + 64];                                             \
        float4 v3 = sb[lane + 96];                                             \
        __stcs((float4*)gf0, v0);                                              \
        __stcs((float4*)gf1, v1);                                              \
        __stcs((float4*)gf2, v2);                                              \
        if (p3) __stcs((float4*)gf3, v3);                                      \
        gf0 += 5 * cs; gf1 += 5 * cs; gf2 += 5 * cs; gf3 += 5 * cs;            \
    }

#pragma unroll 1
    for (int t = 0; t < N_PULSES; ++t) {
        if (fullwarp && t > 0)
            FLUSH((t - 1) & 1)          // data one full step old: LDS lat hidden

        const u64* tp = s_tp[t];
        const u64 tp0 = tp[0], tp1 = tp[1], tp2 = tp[2], tp3 = tp[3];
        const u64 tp4 = tp[4], tp5 = tp[5], tp6 = tp[6];
        float aflip, dummy;
        upk(tp[7], aflip, dummy);

        ADVANCE(A, FpnA, FpinA, FmnA, FminA, ZnA)
        u64 sFprA = __shfl_up_sync(0xffffffffu, FpnA, 1);
        u64 sFpiA = __shfl_up_sync(0xffffffffu, FpinA, 1);
        u64 sFmrA = __shfl_down_sync(0xffffffffu, FmnA, 1);
        u64 sFmiA = __shfl_down_sync(0xffffffffu, FminA, 1);

        ADVANCE(B, FpnB, FpinB, FmnB, FminB, ZnB)
        u64 sFprB = __shfl_up_sync(0xffffffffu, FpnB, 1);
        u64 sFpiB = __shfl_up_sync(0xffffffffu, FpinB, 1);
        u64 sFmrB = __shfl_down_sync(0xffffffffu, FmnB, 1);
        u64 sFmiB = __shfl_down_sync(0xffffffffu, FminB, 1);

        if (edgeFp) { sFprA = 0ull; sFpiA = 0ull; sFprB = 0ull; sFpiB = 0ull; }
        if (edgeFm) { sFmrA = 0ull; sFmiA = 0ull; sFmrB = 0ull; sFmiB = 0ull; }
        FprA = sFprA; FpiA = sFpiA; FmrA = sFmrA; FmiA = sFmiA; ZA = ZnA;
        FprB = sFprB; FpiB = sFpiB; FmrB = sFmrB; FmiB = sFmiB; ZB = ZnB;

        if (fullwarp) {
            if (t & 1) STAGE(st1) else STAGE(st0)
            __syncwarp();
        } else if (active) {
            float l0,h0,l1,h1,l2,h2,l3,h3,l4,h4;
            float* ot = oA + (size_t)t * 5u * cs;
            upk(FprA,l0,h0); upk(FpiA,l1,h1); upk(FmrA,l2,h2);
            upk(FmiA,l3,h3); upk(ZA, l4,h4);
            ot[0] = l0; ot[cs] = l1; ot[2*cs] = l2; ot[3*cs] = l3; ot[4*cs] = l4;
            if (hiA) {
                ot[N_STATES] = h0; ot[N_STATES+cs] = h1; ot[N_STATES+2*cs] = h2;
                ot[N_STATES+3*cs] = h3; ot[N_STATES+4*cs] = h4;
            }
            if (okB) {
                upk(FprB,l0,h0); upk(FpiB,l1,h1); upk(FmrB,l2,h2);
                upk(FmiB,l3,h3); upk(ZB, l4,h4);
                ot[2*N_STATES] = l0; ot[2*N_STATES+cs] = l1;
                ot[2*N_STATES+2*cs] = l2; ot[2*N_STATES+3*cs] = l3;
                ot[2*N_STATES+4*cs] = l4;
                if (hiB) {
                    ot[3*N_STATES] = h0; ot[3*N_STATES+cs] = h1;
                    ot[3*N_STATES+2*cs] = h2; ot[3*N_STATES+3*cs] = h3;
                    ot[3*N_STATES+4*cs] = h4;
                }
            }
        }
    }
    if (fullwarp)
        FLUSH((N_PULSES - 1) & 1)       // final buffer
#undef ADVANCE
#undef STAGE
#undef FLUSH
}

extern "C" void kernel_launch(void* const* d_in, const int* in_sizes, int n_in,
                              void* d_out, int out_size)
{
    const float* flip   = (const float*)d_in[0];
    const float* phases = (const float*)d_in[1];
    const float* T1     = (const float*)d_in[2];
    const float* T2     = (const float*)d_in[3];
    const float* B0     = (const float*)d_in[4];
    const float* B1     = (const float*)d_in[5];
    const void*  TRp    = d_in[6];

    const int nbatch = in_sizes[2];
    float* out = (float*)d_out;
    const int nwarps = (nbatch + 3) / 4;
    const int blocks = (nwarps + WPB - 1) / WPB;
    epg_kernel<<<blocks, THREADS>>>(flip, phases, T1, T2, B0, B1, TRp, out, nbatch);
}